// round 15
// baseline (speedup 1.0000x reference)
#include <cuda_runtime.h>
#include <cuda_fp16.h>
#include <stdint.h>
#include <math.h>

// Problem constants
#define TT 256
#define BB 128
#define DD 300
#define HH 256
#define GG 1024   // 4*H
#define HH2 512   // 2*H
#define TBROWS 32768  // T*B

#define SLICES 8   // rec: n-slices of hidden dim (32 units each)
#define NBG 8      // rec: batch groups
#define BPC 16     // rec: batches per CTA

#define KPAD0 320  // layer-0 K (300) padded to mult of 64
#define KPAD1 512

typedef unsigned long long ull;

// -------- static device scratch (no allocation allowed) --------
__device__ float g_xgF[TBROWS * (size_t)GG];
__device__ float g_xgR[TBROWS * (size_t)GG];
__device__ float g_h2[TBROWS * (size_t)HH2];
__device__ float g_scores[BB * TT];

// fp16 split operand buffers
__device__ __half g_axh[TBROWS * (size_t)KPAD0];   // x hi
__device__ __half g_axl[TBROWS * (size_t)KPAD0];   // x lo
__device__ __half g_ahh[TBROWS * (size_t)KPAD1];   // h1/h2 hi (written by rec3)
__device__ __half g_ahl[TBROWS * (size_t)KPAD1];   // h1/h2 lo (written by rec3)

// weight buffers (element offsets); only hi used for W in GEMMs
#define OFF_L0F 0
#define OFF_L0R 327680                    // 1024*320
#define OFF_L1F 655360
#define OFF_L1R 1179648                   // + 1024*512
#define OFF_MLP 1703936
#define WBUF_SZ 1966080
__device__ __half g_wbh[WBUF_SZ];
__device__ __half g_wbl[WBUF_SZ];

// rec h exchange: fp16 hi/lo [parity][group][b][u]
__device__ __half g_hxh[2][16][BPC][256];
__device__ __half g_hxl[2][16][BPC][256];
// per-CTA arrival flags: [group][slice][32-uint pad] (one 128B line each)
__device__ unsigned g_flag[16 * SLICES * 32];

// ---------------- misc helpers ----------------
__device__ __forceinline__ unsigned ld_acq(const unsigned* p) {
    unsigned v;
    asm volatile("ld.acquire.gpu.global.b32 %0, [%1];" : "=r"(v) : "l"(p) : "memory");
    return v;
}
__device__ __forceinline__ void st_rel(unsigned* p, unsigned v) {
    asm volatile("st.release.gpu.global.b32 [%0], %1;" :: "l"(p), "r"(v) : "memory");
}
__device__ __forceinline__ float sigfast(float x) {
    return __fdividef(1.f, 1.f + __expf(-x));
}
__device__ __forceinline__ float tanhfast(float x) {
    return __fmaf_rn(2.f, __fdividef(1.f, 1.f + __expf(-2.f * x)), -1.f);
}

// ---------------- mma.sync / ldmatrix / cp.async helpers ----------------
__device__ __forceinline__ uint32_t s2u(const void* p) {
    uint32_t a;
    asm("{ .reg .u64 t; cvta.to.shared.u64 t, %1; cvt.u32.u64 %0, t; }" : "=r"(a) : "l"(p));
    return a;
}
__device__ __forceinline__ void cp16(uint32_t s, const void* g) {
    asm volatile("cp.async.cg.shared.global [%0], [%1], 16;" :: "r"(s), "l"(g));
}
#define CP_COMMIT() asm volatile("cp.async.commit_group;" ::: "memory")
#define CP_WAIT1()  asm volatile("cp.async.wait_group 1;" ::: "memory")
#define CP_WAIT0()  asm volatile("cp.async.wait_group 0;" ::: "memory")

#define LDSM4(r, addr) \
    asm volatile("ldmatrix.sync.aligned.m8n8.x4.shared.b16 {%0,%1,%2,%3}, [%4];" \
        : "=r"((r)[0]), "=r"((r)[1]), "=r"((r)[2]), "=r"((r)[3]) : "r"(addr))

#define MMA16816(c, a, b0v, b1v) \
    asm volatile("mma.sync.aligned.m16n8k16.row.col.f32.f16.f16.f32 " \
        "{%0,%1,%2,%3}, {%4,%5,%6,%7}, {%8,%9}, {%0,%1,%2,%3};" \
        : "+f"((c)[0]), "+f"((c)[1]), "+f"((c)[2]), "+f"((c)[3]) \
        : "r"((a)[0]), "r"((a)[1]), "r"((a)[2]), "r"((a)[3]), "r"(b0v), "r"(b1v))

#define SW128(off) ((off) ^ (((off) >> 3) & 0x70))

// ---------------------------------------------------------------
__global__ void zero_flags() {
    int i = blockIdx.x * blockDim.x + threadIdx.x;
    if (i < 16 * SLICES * 32) g_flag[i] = 0u;
}

// ---------------------------------------------------------------
// fp32 -> fp16 hi/lo split with K zero-padding
// ---------------------------------------------------------------
__global__ void conv_split(const float* __restrict__ in,
                           __half* __restrict__ oh,
                           __half* __restrict__ ol,
                           int K, int Kpad, int rows) {
    size_t idx = (size_t)blockIdx.x * blockDim.x + threadIdx.x;
    size_t total = (size_t)rows * Kpad;
    if (idx >= total) return;
    int k = (int)(idx % Kpad);
    size_t row = idx / Kpad;
    float v = (k < K) ? in[row * K + k] : 0.f;
    __half h = __float2half_rn(v);
    oh[idx] = h;
    ol[idx] = __float2half_rn(v - __half2float(h));
}

// ---------------------------------------------------------------
// Tensor-core GEMM (unchanged from rounds 9-14; at HMMA envelope)
// ---------------------------------------------------------------
#define GT_STAGE 49152
#define GT_SMEM (2 * GT_STAGE)   // 98304

__global__ void __launch_bounds__(256, 2)
gemm_tc(int a_sel, int woff, int Kpad, int nc, int dst_sel,
        const float* __restrict__ bias1, const float* __restrict__ bias2,
        const float* __restrict__ ctx) {
    extern __shared__ char sm[];
    const uint32_t smb = s2u(sm);
    const int tid = threadIdx.x;
    const int lane = tid & 31;
    const int wid = tid >> 5;
    const int warp_m = wid & 3;
    const int warp_n = wid >> 2;

    const __half* __restrict__ Ah = a_sel ? g_ahh : g_axh;
    const __half* __restrict__ Al = a_sel ? g_ahl : g_axl;
    const __half* __restrict__ Wh = g_wbh + woff;

    const int m0 = blockIdx.x * 128;
    const int n0 = blockIdx.y * 128;

    const int lrow = tid >> 1;
    const int lj0 = (tid & 1) * 4;
    const size_t aoff = (size_t)(m0 + lrow) * Kpad;
    const size_t woff2 = (size_t)(n0 + lrow) * Kpad;

    float acc[2][8][4];
#pragma unroll
    for (int i = 0; i < 2; ++i)
#pragma unroll
        for (int j = 0; j < 8; ++j)
#pragma unroll
            for (int k = 0; k < 4; ++k) acc[i][j][k] = 0.f;

    {
        const uint4* pAh = (const uint4*)(Ah + aoff);
        const uint4* pAl = (const uint4*)(Al + aoff);
        const uint4* pWh = (const uint4*)(Wh + woff2);
#pragma unroll
        for (int j = 0; j < 4; ++j) {
            uint32_t so = SW128((uint32_t)(lrow * 128 + (lj0 + j) * 16));
            cp16(smb + so,         pAh + lj0 + j);
            cp16(smb + 16384 + so, pAl + lj0 + j);
            cp16(smb + 32768 + so, pWh + lj0 + j);
        }
        CP_COMMIT();
    }

    for (int c = 0; c < nc; ++c) {
        if (c + 1 < nc) {
            uint32_t sb = smb + ((c + 1) & 1) * GT_STAGE;
            const uint4* pAh = (const uint4*)(Ah + aoff + (c + 1) * 64);
            const uint4* pAl = (const uint4*)(Al + aoff + (c + 1) * 64);
            const uint4* pWh = (const uint4*)(Wh + woff2 + (c + 1) * 64);
#pragma unroll
            for (int j = 0; j < 4; ++j) {
                uint32_t so = SW128((uint32_t)(lrow * 128 + (lj0 + j) * 16));
                cp16(sb + so,         pAh + lj0 + j);
                cp16(sb + 16384 + so, pAl + lj0 + j);
                cp16(sb + 32768 + so, pWh + lj0 + j);
            }
            CP_COMMIT();
            CP_WAIT1();
        } else {
            CP_WAIT0();
        }
        __syncthreads();

        const uint32_t bb = smb + (c & 1) * GT_STAGE;
        const int rowb_base = warp_n * 64 + (lane & 7) + ((lane >> 4) << 3);
        const int kbb_half = ((lane >> 3) & 1) * 16;
        const int rowa_base = warp_m * 32 + (lane & 15);
        const int kba_half = (lane >> 4) * 16;

#pragma unroll
        for (int ks = 0; ks < 4; ++ks) {
            uint32_t ah[2][4], al[2][4], wh[4][4];
            const int kba = ks * 32 + kba_half;
#pragma unroll
            for (int mf = 0; mf < 2; ++mf) {
                uint32_t off = SW128((uint32_t)((rowa_base + mf * 16) * 128 + kba));
                LDSM4(ah[mf], bb + off);
                LDSM4(al[mf], bb + 16384 + off);
            }
            const int kbbs = ks * 32 + kbb_half;
#pragma unroll
            for (int nf4 = 0; nf4 < 4; ++nf4) {
                uint32_t off = SW128((uint32_t)((rowb_base + nf4 * 16) * 128 + kbbs));
                LDSM4(wh[nf4], bb + 32768 + off);
            }
#pragma unroll
            for (int nf4 = 0; nf4 < 4; ++nf4)
#pragma unroll
                for (int mf = 0; mf < 2; ++mf) {
                    MMA16816(acc[mf][nf4 * 2],     ah[mf], wh[nf4][0], wh[nf4][1]);
                    MMA16816(acc[mf][nf4 * 2 + 1], ah[mf], wh[nf4][2], wh[nf4][3]);
                }
#pragma unroll
            for (int nf4 = 0; nf4 < 4; ++nf4)
#pragma unroll
                for (int mf = 0; mf < 2; ++mf) {
                    MMA16816(acc[mf][nf4 * 2],     al[mf], wh[nf4][0], wh[nf4][1]);
                    MMA16816(acc[mf][nf4 * 2 + 1], al[mf], wh[nf4][2], wh[nf4][3]);
                }
        }
        __syncthreads();
    }

    const int g4 = lane >> 2, q = lane & 3;
    if (dst_sel < 2) {
        float* __restrict__ dst = dst_sel ? g_xgR : g_xgF;
#pragma unroll
        for (int nf = 0; nf < 8; ++nf) {
            int n = n0 + warp_n * 64 + nf * 8 + q * 2;
            float bv0 = bias1[n] + bias2[n];
            float bv1 = bias1[n + 1] + bias2[n + 1];
#pragma unroll
            for (int mf = 0; mf < 2; ++mf) {
                int r_ = m0 + warp_m * 32 + mf * 16 + g4;
                *(float2*)&dst[(size_t)r_ * GG + n] =
                    make_float2(acc[mf][nf][0] + bv0, acc[mf][nf][1] + bv1);
                *(float2*)&dst[(size_t)(r_ + 8) * GG + n] =
                    make_float2(acc[mf][nf][2] + bv0, acc[mf][nf][3] + bv1);
            }
        }
    } else {
        float sacc[4] = {0.f, 0.f, 0.f, 0.f};
#pragma unroll
        for (int nf = 0; nf < 8; ++nf) {
            int n = n0 + warp_n * 64 + nf * 8 + q * 2;
            float bv0 = bias1[n], bv1 = bias1[n + 1];
            float c0 = ctx[n], c1 = ctx[n + 1];
#pragma unroll
            for (int mf = 0; mf < 2; ++mf) {
                sacc[mf * 2 + 0] += tanhf(acc[mf][nf][0] + bv0) * c0
                                  + tanhf(acc[mf][nf][1] + bv1) * c1;
                sacc[mf * 2 + 1] += tanhf(acc[mf][nf][2] + bv0) * c0
                                  + tanhf(acc[mf][nf][3] + bv1) * c1;
            }
        }
#pragma unroll
        for (int s = 0; s < 4; ++s) {
            float v = sacc[s];
            v += __shfl_xor_sync(0xffffffffu, v, 1);
            v += __shfl_xor_sync(0xffffffffu, v, 2);
            if (q == 0) {
                int mf = s >> 1, rp = s & 1;
                int r_ = m0 + warp_m * 32 + mf * 16 + g4 + rp * 8;
                atomicAdd(&g_scores[(r_ & 127) * TT + (r_ >> 7)], v);
            }
        }
    }
}

// ---------------------------------------------------------------
// Recurrence v8: tensor-core matvec with chunk-pipelined rebuild.
// Each step's MMA loop consumes k-chunks just-in-time: warps 2kc,2kc+1
// poll producer flags for slices 2kc,2kc+1 and rebuild chunk kc right
// before it's needed, hiding the flag+L2 latency behind MMAs of earlier
// chunks. st.release (no separate threadfence) publishes exchange data.
//
// SMEM: Whh 65536 | Whl 65536 | Ahh 8192 | Ahl 8192 | Dsm [16][132]f 8448
//       | lensm 64  => 155968 B
// ---------------------------------------------------------------
#define R3_WHH 0
#define R3_WHL 65536
#define R3_AHH 131072
#define R3_AHL 139264
#define R3_DSM 147456
#define R3_LEN 155904
#define REC3_SMEM 155968

__global__ void __launch_bounds__(256, 1)
rec3(const int* __restrict__ lengths,
     const float* __restrict__ whh_f, const float* __restrict__ whh_r,
     int layer) {
    extern __shared__ char smraw[];
    const uint32_t smb = s2u(smraw);
    float* Dsm = (float*)(smraw + R3_DSM);
    int* lensm = (int*)(smraw + R3_LEN);

    const int slice = blockIdx.x, bg = blockIdx.y, dir = blockIdx.z;
    const int tid = threadIdx.x;
    const int wid = tid >> 5;
    const int lane = tid & 31;
    const int gid = dir * NBG + bg;

    const float* __restrict__ whh = dir ? whh_r : whh_f;
    const float* __restrict__ xg = dir ? g_xgR : g_xgF;

    // ---- one-time W slice load + fp16 split into SW128 chunks ----
    {
        int n = tid >> 1;                              // local n row 0..127
        int grow = (n >> 5) * 256 + slice * 32 + (n & 31);
        int kh = (tid & 1) * 128;
        const float* src = whh + (size_t)grow * HH + kh;
#pragma unroll 8
        for (int kk = 0; kk < 128; kk += 2) {
            int k = kh + kk;
            float2 v = *(const float2*)(src + kk);
            __half2 hi = __float22half2_rn(v);
            float2 hif = __half22float2(hi);
            __half2 lo = __float22half2_rn(make_float2(v.x - hif.x, v.y - hif.y));
            int kc = k >> 6;
            uint32_t off = SW128((uint32_t)(n * 128 + (k & 63) * 2));
            *(__half2*)(smraw + R3_WHH + kc * 16384 + off) = hi;
            *(__half2*)(smraw + R3_WHL + kc * 16384 + off) = lo;
        }
    }
    // zero A chunks (h(-1) = 0)
    for (int i = tid; i < 2048; i += 256) {
        ((__half2*)(smraw + R3_AHH))[i] = __halves2half2(__float2half(0.f), __float2half(0.f));
        ((__half2*)(smraw + R3_AHL))[i] = __halves2half2(__float2half(0.f), __float2half(0.f));
    }
    if (tid < 16) {
        int l = lengths[bg * BPC + tid];
        lensm[tid] = l < 1 ? 1 : l;
    }
    __syncthreads();

    // frag addressing (identical pattern to gemm_tc)
    const int g4 = lane >> 2, q = lane & 3;
    const int rowb = wid * 16 + (lane & 7) + ((lane >> 4) << 3);
    const int kbb = ((lane >> 3) & 1) * 16;
    const int rowa = lane & 15;
    const int kba = (lane >> 4) * 16;

    // this lane's two frag n-columns and their xg columns
    int ncol[2], xcol[2];
#pragma unroll
    for (int f = 0; f < 2; ++f) {
        ncol[f] = wid * 16 + f * 8 + 2 * q;
        xcol[f] = ((ncol[f] >> 5) << 8) + slice * 32 + (ncol[f] & 31);
    }
    const int mrow0 = g4, mrow1 = g4 + 8;   // batch rows of the frags

    // pointwise slot
    const int my_bs = tid & 15;
    const int my_u2 = tid >> 4;
    const int my_u = slice * 32 + 2 * my_u2;
    unsigned* my_flag = &g_flag[(gid * SLICES + slice) * 32];
    const unsigned* warp_flag = &g_flag[(gid * SLICES + wid) * 32];

    // rebuild region: batch b = tid&15, k-range [k0, k0+16); chunk = wid>>1
    const int rb_b = tid & 15;
    const int rb_k0 = (tid >> 4) * 16;
    const int rb_kc = rb_k0 >> 6;           // == wid >> 1
    const int my_kc = wid >> 1;
    const uint32_t rb_off0 = SW128((uint32_t)(rb_b * 128 + (rb_k0 & 63) * 2));
    const uint32_t rb_off1 = SW128((uint32_t)(rb_b * 128 + (rb_k0 & 63) * 2 + 16));

    float c0 = 0.f, c1 = 0.f;

    // xg frag preload for t = 0
    float xf[2][4];
    {
        int len0 = lensm[mrow0], len1 = lensm[mrow1];
        int t0 = dir ? (len0 - 1) : 0;
        int t1 = dir ? (len1 - 1) : 0;
#pragma unroll
        for (int f = 0; f < 2; ++f) {
            float2 a = *(const float2*)(xg + ((size_t)t0 * BB + bg * BPC + mrow0) * GG + xcol[f]);
            float2 b = *(const float2*)(xg + ((size_t)t1 * BB + bg * BPC + mrow1) * GG + xcol[f]);
            xf[f][0] = a.x; xf[f][1] = a.y; xf[f][2] = b.x; xf[f][3] = b.y;
        }
    }

    for (int t = 0; t < TT; ++t) {
        // ---- matvec with just-in-time chunk rebuild ----
        float acc[2][4];
#pragma unroll
        for (int f = 0; f < 2; ++f)
#pragma unroll
            for (int i = 0; i < 4; ++i) acc[f][i] = xf[f][i];

#pragma unroll
        for (int kc = 0; kc < 4; ++kc) {
            if (t > 0 && my_kc == kc) {
                unsigned target = (unsigned)t;
                while (ld_acq(warp_flag) < target) {}
                const uint4* srcH = (const uint4*)&g_hxh[(t - 1) & 1][gid][rb_b][rb_k0];
                const uint4* srcL = (const uint4*)&g_hxl[(t - 1) & 1][gid][rb_b][rb_k0];
                uint4 vh0 = __ldcg(srcH);
                uint4 vh1 = __ldcg(srcH + 1);
                uint4 vl0 = __ldcg(srcL);
                uint4 vl1 = __ldcg(srcL + 1);
                *(uint4*)(smraw + R3_AHH + rb_kc * 2048 + rb_off0) = vh0;
                *(uint4*)(smraw + R3_AHH + rb_kc * 2048 + rb_off1) = vh1;
                *(uint4*)(smraw + R3_AHL + rb_kc * 2048 + rb_off0) = vl0;
                *(uint4*)(smraw + R3_AHL + rb_kc * 2048 + rb_off1) = vl1;
            }
            __syncthreads();
#pragma unroll
            for (int ks = 0; ks < 4; ++ks) {
                uint32_t ah[4], al[4], wh[4], wl[4];
                uint32_t ao = SW128((uint32_t)(rowa * 128 + ks * 32 + kba));
                LDSM4(ah, smb + R3_AHH + kc * 2048 + ao);
                LDSM4(al, smb + R3_AHL + kc * 2048 + ao);
                uint32_t bo = SW128((uint32_t)(rowb * 128 + ks * 32 + kbb));
                LDSM4(wh, smb + R3_WHH + kc * 16384 + bo);
                LDSM4(wl, smb + R3_WHL + kc * 16384 + bo);
                MMA16816(acc[0], ah, wh[0], wh[1]);
                MMA16816(acc[1], ah, wh[2], wh[3]);
                MMA16816(acc[0], al, wh[0], wh[1]);
                MMA16816(acc[1], al, wh[2], wh[3]);
                MMA16816(acc[0], ah, wl[0], wl[1]);
                MMA16816(acc[1], ah, wl[2], wl[3]);
            }
        }

        // ---- stage gates to Dsm ----
#pragma unroll
        for (int f = 0; f < 2; ++f) {
            *(float2*)&Dsm[mrow0 * 132 + ncol[f]] = make_float2(acc[f][0], acc[f][1]);
            *(float2*)&Dsm[mrow1 * 132 + ncol[f]] = make_float2(acc[f][2], acc[f][3]);
        }
        __syncthreads();

        // ---- pointwise LSTM cell for slot (my_bs, my_u2) ----
        float h0, h1;
        {
            float2 vgi = *(const float2*)&Dsm[my_bs * 132 + 0 * 32 + 2 * my_u2];
            float2 vgf = *(const float2*)&Dsm[my_bs * 132 + 1 * 32 + 2 * my_u2];
            float2 vgc = *(const float2*)&Dsm[my_bs * 132 + 2 * 32 + 2 * my_u2];
            float2 vgo = *(const float2*)&Dsm[my_bs * 132 + 3 * 32 + 2 * my_u2];
            float i0 = sigfast(vgi.x), i1 = sigfast(vgi.y);
            float f0 = sigfast(vgf.x), f1 = sigfast(vgf.y);
            float z0 = tanhfast(vgc.x), z1 = tanhfast(vgc.y);
            float o0 = sigfast(vgo.x), o1 = sigfast(vgo.y);
            c0 = f0 * c0 + i0 * z0;
            c1 = f1 * c1 + i1 * z1;
            h0 = o0 * tanhfast(c0);
            h1 = o1 * tanhfast(c1);
        }

        // fp16 hi/lo split of h (used for exchange AND global outputs)
        __half2 hi2, lo2;
        {
            __half h0h = __float2half_rn(h0);
            __half h1h = __float2half_rn(h1);
            hi2 = __halves2half2(h0h, h1h);
            lo2 = __halves2half2(__float2half_rn(h0 - __half2float(h0h)),
                                 __float2half_rn(h1 - __half2float(h1h)));
        }

        if (t + 1 < TT) {
            // exchange store (fp16 hi/lo) + release-arrive
            __stcg((uint32_t*)&g_hxh[t & 1][gid][my_bs][my_u], *(uint32_t*)&hi2);
            __stcg((uint32_t*)&g_hxl[t & 1][gid][my_bs][my_u], *(uint32_t*)&lo2);
            __syncthreads();
            if (tid == 0) st_rel(my_flag, (unsigned)(t + 1));
        }

        // ---- global outputs + xg frag prefetch (hidden in peers' window) ----
        {
            int len = lensm[my_bs];
            int tin = dir ? ((t < len) ? (len - 1 - t) : t) : t;
            size_t aoff2 = ((size_t)tin * BB + bg * BPC + my_bs) * HH2 + dir * HH + my_u;
            *(__half2*)(g_ahh + aoff2) = hi2;
            *(__half2*)(g_ahl + aoff2) = lo2;
            if (layer)
                *(float2*)(g_h2 + aoff2) = make_float2(h0, h1);
        }

        if (t + 1 < TT) {
            int tn = t + 1;
            int len0 = lensm[mrow0], len1 = lensm[mrow1];
            int t0 = dir ? ((tn < len0) ? (len0 - 1 - tn) : tn) : tn;
            int t1 = dir ? ((tn < len1) ? (len1 - 1 - tn) : tn) : tn;
#pragma unroll
            for (int f = 0; f < 2; ++f) {
                float2 a = *(const float2*)(xg + ((size_t)t0 * BB + bg * BPC + mrow0) * GG + xcol[f]);
                float2 b = *(const float2*)(xg + ((size_t)t1 * BB + bg * BPC + mrow1) * GG + xcol[f]);
                xf[f][0] = a.x; xf[f][1] = a.y; xf[f][2] = b.x; xf[f][3] = b.y;
            }
        }
    }
}

// ---------------------------------------------------------------
__global__ void zero_scores() {
    int i = blockIdx.x * blockDim.x + threadIdx.x;
    if (i < BB * TT) g_scores[i] = 0.f;
}

// ---------------------------------------------------------------
// Masked softmax over time + weighted sum of h2 -> out [B, 2H].
// ---------------------------------------------------------------
__global__ void __launch_bounds__(256)
attn_out(const int* __restrict__ lengths, float* __restrict__ out) {
    int b = blockIdx.x;
    int tid = threadIdx.x;
    __shared__ float red[256];
    __shared__ float w[256];

    int len = lengths[b];
    if (len < 1) len = 1;

    float s = (tid < len) ? g_scores[b * TT + tid] : -3.0e38f;
    red[tid] = s;
    __syncthreads();
    for (int o = 128; o > 0; o >>= 1) {
        if (tid < o) red[tid] = fmaxf(red[tid], red[tid + o]);
        __syncthreads();
    }
    float mx = red[0];
    __syncthreads();
    float e = (tid < len) ? expf(s - mx) : 0.f;
    red[tid] = e;
    __syncthreads();
    for (int o = 128; o > 0; o >>= 1) {
        if (tid < o) red[tid] += red[tid + o];
        __syncthreads();
    }
    float inv = 1.f / red[0];
    w[tid] = e * inv;
    __syncthreads();

    for (int d = tid; d < HH2; d += 256) {
        float acc = 0.f;
        for (int t = 0; t < len; ++t)
            acc += w[t] * g_h2[((size_t)t * BB + b) * HH2 + d];
        out[b * HH2 + d] = acc;
    }
}

// ---------------------------------------------------------------
extern "C" void kernel_launch(void* const* d_in, const int* in_sizes, int n_in,
                              void* d_out, int out_size) {
    const float* x        = (const float*)d_in[0];
    const int*   lengths  = (const int*)d_in[1];
    const float* w_ih_l0  = (const float*)d_in[2];
    const float* w_hh_l0  = (const float*)d_in[3];
    const float* b_ih_l0  = (const float*)d_in[4];
    const float* b_hh_l0  = (const float*)d_in[5];
    const float* w_ih_l0r = (const float*)d_in[6];
    const float* w_hh_l0r = (const float*)d_in[7];
    const float* b_ih_l0r = (const float*)d_in[8];
    const float* b_hh_l0r = (const float*)d_in[9];
    const float* w_ih_l1  = (const float*)d_in[10];
    const float* w_hh_l1  = (const float*)d_in[11];
    const float* b_ih_l1  = (const float*)d_in[12];
    const float* b_hh_l1  = (const float*)d_in[13];
    const float* w_ih_l1r = (const float*)d_in[14];
    const float* w_hh_l1r = (const float*)d_in[15];
    const float* b_ih_l1r = (const float*)d_in[16];
    const float* b_hh_l1r = (const float*)d_in[17];
    const float* mlp_w    = (const float*)d_in[18];
    const float* mlp_b    = (const float*)d_in[19];
    const float* ctx      = (const float*)d_in[20];
    float* out = (float*)d_out;

    static int attr_set = 0;
    if (!attr_set) {
        cudaFuncSetAttribute(rec3, cudaFuncAttributeMaxDynamicSharedMemorySize, REC3_SMEM);
        cudaFuncSetAttribute(gemm_tc, cudaFuncAttributeMaxDynamicSharedMemorySize, GT_SMEM);
        attr_set = 1;
    }

    __half *wbh, *wbl, *axh, *axl;
    cudaGetSymbolAddress((void**)&wbh, g_wbh);
    cudaGetSymbolAddress((void**)&wbl, g_wbl);
    cudaGetSymbolAddress((void**)&axh, g_axh);
    cudaGetSymbolAddress((void**)&axl, g_axl);

    // converts needed for layer-0 GEMMs
    conv_split<<<(TBROWS * KPAD0 + 255) / 256, 256>>>(x, axh, axl, DD, KPAD0, TBROWS);
    conv_split<<<(1024 * KPAD0 + 255) / 256, 256>>>(w_ih_l0,  wbh + OFF_L0F, wbl + OFF_L0F, DD, KPAD0, 1024);
    conv_split<<<(1024 * KPAD0 + 255) / 256, 256>>>(w_ih_l0r, wbh + OFF_L0R, wbl + OFF_L0R, DD, KPAD0, 1024);

    // layer-0 projection GEMMs
    gemm_tc<<<dim3(256, 8), 256, GT_SMEM>>>(0, OFF_L0F, KPAD0, 5, 0, b_ih_l0,  b_hh_l0,  nullptr);
    gemm_tc<<<dim3(256, 8), 256, GT_SMEM>>>(0, OFF_L0R, KPAD0, 5, 1, b_ih_l0r, b_hh_l0r, nullptr);

    // remaining weight converts
    conv_split<<<(1024 * KPAD1 + 255) / 256, 256>>>(w_ih_l1,  wbh + OFF_L1F, wbl + OFF_L1F, HH2, KPAD1, 1024);
    conv_split<<<(1024 * KPAD1 + 255) / 256, 256>>>(w_ih_l1r, wbh + OFF_L1R, wbl + OFF_L1R, HH2, KPAD1, 1024);

    // layer-0 recurrence (tensor-core matvec, pipelined rebuild)
    zero_flags<<<16, 256>>>();
    rec3<<<dim3(SLICES, NBG, 2), 256, REC3_SMEM>>>(lengths, w_hh_l0, w_hh_l0r, 0);

    // layer-1 projections
    gemm_tc<<<dim3(256, 8), 256, GT_SMEM>>>(1, OFF_L1F, KPAD1, 8, 0, b_ih_l1,  b_hh_l1,  nullptr);
    gemm_tc<<<dim3(256, 8), 256, GT_SMEM>>>(1, OFF_L1R, KPAD1, 8, 1, b_ih_l1r, b_hh_l1r, nullptr);

    // layer-1 recurrence
    zero_flags<<<16, 256>>>();
    rec3<<<dim3(SLICES, NBG, 2), 256, REC3_SMEM>>>(lengths, w_hh_l1, w_hh_l1r, 1);

    // attention
    conv_split<<<(512 * KPAD1 + 255) / 256, 256>>>(mlp_w, wbh + OFF_MLP, wbl + OFF_MLP, HH2, KPAD1, 512);
    zero_scores<<<32, 1024>>>();
    gemm_tc<<<dim3(256, 4), 256, GT_SMEM>>>(1, OFF_MLP, KPAD1, 8, 2, mlp_b, nullptr, ctx);
    attn_out<<<128, 256>>>(lengths, out);
}

// round 16
// speedup vs baseline: 1.4044x; 1.4044x over previous
#include <cuda_runtime.h>
#include <cuda_fp16.h>
#include <stdint.h>
#include <math.h>

// Problem constants
#define TT 256
#define BB 128
#define DD 300
#define HH 256
#define GG 1024   // 4*H
#define HH2 512   // 2*H
#define TBROWS 32768  // T*B

#define SLICES 8   // rec: n-slices of hidden dim (32 units each)
#define NBG 8      // rec: batch groups
#define BPC 16     // rec: batches per CTA

#define KPAD0 320  // layer-0 K (300) padded to mult of 64
#define KPAD1 512

typedef unsigned long long ull;

// -------- static device scratch (no allocation allowed) --------
__device__ float g_xgF[TBROWS * (size_t)GG];
__device__ float g_xgR[TBROWS * (size_t)GG];
__device__ float g_h2[TBROWS * (size_t)HH2];
__device__ float g_scores[BB * TT];

// fp16 split operand buffers
__device__ __half g_axh[TBROWS * (size_t)KPAD0];   // x hi
__device__ __half g_axl[TBROWS * (size_t)KPAD0];   // x lo
__device__ __half g_ahh[TBROWS * (size_t)KPAD1];   // h1/h2 hi (written by rec3)
__device__ __half g_ahl[TBROWS * (size_t)KPAD1];   // h1/h2 lo (written by rec3)

// weight buffers (element offsets); only hi used for W in GEMMs
#define OFF_L0F 0
#define OFF_L0R 327680                    // 1024*320
#define OFF_L1F 655360
#define OFF_L1R 1179648                   // + 1024*512
#define OFF_MLP 1703936
#define WBUF_SZ 1966080
__device__ __half g_wbh[WBUF_SZ];
__device__ __half g_wbl[WBUF_SZ];

// rec h exchange: fp16 hi/lo [parity][group][b][u]
__device__ __half g_hxh[2][16][BPC][256];
__device__ __half g_hxl[2][16][BPC][256];
// per-CTA arrival flags: [group][slice][32-uint pad] (one 128B line each)
__device__ unsigned g_flag[16 * SLICES * 32];

// ---------------- misc helpers ----------------
__device__ __forceinline__ unsigned ld_acq(const unsigned* p) {
    unsigned v;
    asm volatile("ld.acquire.gpu.global.b32 %0, [%1];" : "=r"(v) : "l"(p) : "memory");
    return v;
}
__device__ __forceinline__ void st_rel(unsigned* p, unsigned v) {
    asm volatile("st.release.gpu.global.b32 [%0], %1;" :: "l"(p), "r"(v) : "memory");
}
__device__ __forceinline__ float sigfast(float x) {
    return __fdividef(1.f, 1.f + __expf(-x));
}
__device__ __forceinline__ float tanhfast(float x) {
    return __fmaf_rn(2.f, __fdividef(1.f, 1.f + __expf(-2.f * x)), -1.f);
}

// ---------------- mma.sync / ldmatrix / cp.async helpers ----------------
__device__ __forceinline__ uint32_t s2u(const void* p) {
    uint32_t a;
    asm("{ .reg .u64 t; cvta.to.shared.u64 t, %1; cvt.u32.u64 %0, t; }" : "=r"(a) : "l"(p));
    return a;
}
__device__ __forceinline__ void cp16(uint32_t s, const void* g) {
    asm volatile("cp.async.cg.shared.global [%0], [%1], 16;" :: "r"(s), "l"(g));
}
#define CP_COMMIT() asm volatile("cp.async.commit_group;" ::: "memory")
#define CP_WAIT1()  asm volatile("cp.async.wait_group 1;" ::: "memory")
#define CP_WAIT0()  asm volatile("cp.async.wait_group 0;" ::: "memory")

#define LDSM4(r, addr) \
    asm volatile("ldmatrix.sync.aligned.m8n8.x4.shared.b16 {%0,%1,%2,%3}, [%4];" \
        : "=r"((r)[0]), "=r"((r)[1]), "=r"((r)[2]), "=r"((r)[3]) : "r"(addr))

#define MMA16816(c, a, b0v, b1v) \
    asm volatile("mma.sync.aligned.m16n8k16.row.col.f32.f16.f16.f32 " \
        "{%0,%1,%2,%3}, {%4,%5,%6,%7}, {%8,%9}, {%0,%1,%2,%3};" \
        : "+f"((c)[0]), "+f"((c)[1]), "+f"((c)[2]), "+f"((c)[3]) \
        : "r"((a)[0]), "r"((a)[1]), "r"((a)[2]), "r"((a)[3]), "r"(b0v), "r"(b1v))

#define SW128(off) ((off) ^ (((off) >> 3) & 0x70))

// ---------------------------------------------------------------
__global__ void zero_flags() {
    int i = blockIdx.x * blockDim.x + threadIdx.x;
    if (i < 16 * SLICES * 32) g_flag[i] = 0u;
}

// ---------------------------------------------------------------
// fp32 -> fp16 hi/lo split with K zero-padding
// ---------------------------------------------------------------
__global__ void conv_split(const float* __restrict__ in,
                           __half* __restrict__ oh,
                           __half* __restrict__ ol,
                           int K, int Kpad, int rows) {
    size_t idx = (size_t)blockIdx.x * blockDim.x + threadIdx.x;
    size_t total = (size_t)rows * Kpad;
    if (idx >= total) return;
    int k = (int)(idx % Kpad);
    size_t row = idx / Kpad;
    float v = (k < K) ? in[row * K + k] : 0.f;
    __half h = __float2half_rn(v);
    oh[idx] = h;
    ol[idx] = __float2half_rn(v - __half2float(h));
}

// ---------------------------------------------------------------
// Tensor-core GEMM (mma.sync fp16, 2-term split AhWh + AlWh).
// gridDim.z selects fwd/rev weight set + destination: z=0 -> (woff, b1, b2,
// dst g_xgF); z=1 -> (woffR, b1R, b2R, dst g_xgR). dst_sel=2 = attention
// scores path (launch with gridDim.z=1).
// ---------------------------------------------------------------
#define GT_STAGE 49152
#define GT_SMEM (2 * GT_STAGE)   // 98304

__global__ void __launch_bounds__(256, 2)
gemm_tc(int a_sel, int woff, int Kpad, int nc, int dst_sel,
        const float* __restrict__ bias1, const float* __restrict__ bias2,
        const float* __restrict__ ctx,
        int woffR,
        const float* __restrict__ bias1R, const float* __restrict__ bias2R) {
    extern __shared__ char sm[];
    const uint32_t smb = s2u(sm);
    const int tid = threadIdx.x;
    const int lane = tid & 31;
    const int wid = tid >> 5;
    const int warp_m = wid & 3;
    const int warp_n = wid >> 2;

    if (blockIdx.z == 1) {
        woff = woffR;
        bias1 = bias1R;
        bias2 = bias2R;
        dst_sel = 1;
    }

    const __half* __restrict__ Ah = a_sel ? g_ahh : g_axh;
    const __half* __restrict__ Al = a_sel ? g_ahl : g_axl;
    const __half* __restrict__ Wh = g_wbh + woff;

    const int m0 = blockIdx.x * 128;
    const int n0 = blockIdx.y * 128;

    const int lrow = tid >> 1;
    const int lj0 = (tid & 1) * 4;
    const size_t aoff = (size_t)(m0 + lrow) * Kpad;
    const size_t woff2 = (size_t)(n0 + lrow) * Kpad;

    float acc[2][8][4];
#pragma unroll
    for (int i = 0; i < 2; ++i)
#pragma unroll
        for (int j = 0; j < 8; ++j)
#pragma unroll
            for (int k = 0; k < 4; ++k) acc[i][j][k] = 0.f;

    {
        const uint4* pAh = (const uint4*)(Ah + aoff);
        const uint4* pAl = (const uint4*)(Al + aoff);
        const uint4* pWh = (const uint4*)(Wh + woff2);
#pragma unroll
        for (int j = 0; j < 4; ++j) {
            uint32_t so = SW128((uint32_t)(lrow * 128 + (lj0 + j) * 16));
            cp16(smb + so,         pAh + lj0 + j);
            cp16(smb + 16384 + so, pAl + lj0 + j);
            cp16(smb + 32768 + so, pWh + lj0 + j);
        }
        CP_COMMIT();
    }

    for (int c = 0; c < nc; ++c) {
        if (c + 1 < nc) {
            uint32_t sb = smb + ((c + 1) & 1) * GT_STAGE;
            const uint4* pAh = (const uint4*)(Ah + aoff + (c + 1) * 64);
            const uint4* pAl = (const uint4*)(Al + aoff + (c + 1) * 64);
            const uint4* pWh = (const uint4*)(Wh + woff2 + (c + 1) * 64);
#pragma unroll
            for (int j = 0; j < 4; ++j) {
                uint32_t so = SW128((uint32_t)(lrow * 128 + (lj0 + j) * 16));
                cp16(sb + so,         pAh + lj0 + j);
                cp16(sb + 16384 + so, pAl + lj0 + j);
                cp16(sb + 32768 + so, pWh + lj0 + j);
            }
            CP_COMMIT();
            CP_WAIT1();
        } else {
            CP_WAIT0();
        }
        __syncthreads();

        const uint32_t bb = smb + (c & 1) * GT_STAGE;
        const int rowb_base = warp_n * 64 + (lane & 7) + ((lane >> 4) << 3);
        const int kbb_half = ((lane >> 3) & 1) * 16;
        const int rowa_base = warp_m * 32 + (lane & 15);
        const int kba_half = (lane >> 4) * 16;

#pragma unroll
        for (int ks = 0; ks < 4; ++ks) {
            uint32_t ah[2][4], al[2][4], wh[4][4];
            const int kba = ks * 32 + kba_half;
#pragma unroll
            for (int mf = 0; mf < 2; ++mf) {
                uint32_t off = SW128((uint32_t)((rowa_base + mf * 16) * 128 + kba));
                LDSM4(ah[mf], bb + off);
                LDSM4(al[mf], bb + 16384 + off);
            }
            const int kbbs = ks * 32 + kbb_half;
#pragma unroll
            for (int nf4 = 0; nf4 < 4; ++nf4) {
                uint32_t off = SW128((uint32_t)((rowb_base + nf4 * 16) * 128 + kbbs));
                LDSM4(wh[nf4], bb + 32768 + off);
            }
#pragma unroll
            for (int nf4 = 0; nf4 < 4; ++nf4)
#pragma unroll
                for (int mf = 0; mf < 2; ++mf) {
                    MMA16816(acc[mf][nf4 * 2],     ah[mf], wh[nf4][0], wh[nf4][1]);
                    MMA16816(acc[mf][nf4 * 2 + 1], ah[mf], wh[nf4][2], wh[nf4][3]);
                }
#pragma unroll
            for (int nf4 = 0; nf4 < 4; ++nf4)
#pragma unroll
                for (int mf = 0; mf < 2; ++mf) {
                    MMA16816(acc[mf][nf4 * 2],     al[mf], wh[nf4][0], wh[nf4][1]);
                    MMA16816(acc[mf][nf4 * 2 + 1], al[mf], wh[nf4][2], wh[nf4][3]);
                }
        }
        __syncthreads();
    }

    const int g4 = lane >> 2, q = lane & 3;
    if (dst_sel < 2) {
        float* __restrict__ dst = dst_sel ? g_xgR : g_xgF;
#pragma unroll
        for (int nf = 0; nf < 8; ++nf) {
            int n = n0 + warp_n * 64 + nf * 8 + q * 2;
            float bv0 = bias1[n] + bias2[n];
            float bv1 = bias1[n + 1] + bias2[n + 1];
#pragma unroll
            for (int mf = 0; mf < 2; ++mf) {
                int r_ = m0 + warp_m * 32 + mf * 16 + g4;
                *(float2*)&dst[(size_t)r_ * GG + n] =
                    make_float2(acc[mf][nf][0] + bv0, acc[mf][nf][1] + bv1);
                *(float2*)&dst[(size_t)(r_ + 8) * GG + n] =
                    make_float2(acc[mf][nf][2] + bv0, acc[mf][nf][3] + bv1);
            }
        }
    } else {
        float sacc[4] = {0.f, 0.f, 0.f, 0.f};
#pragma unroll
        for (int nf = 0; nf < 8; ++nf) {
            int n = n0 + warp_n * 64 + nf * 8 + q * 2;
            float bv0 = bias1[n], bv1 = bias1[n + 1];
            float c0 = ctx[n], c1 = ctx[n + 1];
#pragma unroll
            for (int mf = 0; mf < 2; ++mf) {
                sacc[mf * 2 + 0] += tanhf(acc[mf][nf][0] + bv0) * c0
                                  + tanhf(acc[mf][nf][1] + bv1) * c1;
                sacc[mf * 2 + 1] += tanhf(acc[mf][nf][2] + bv0) * c0
                                  + tanhf(acc[mf][nf][3] + bv1) * c1;
            }
        }
#pragma unroll
        for (int s = 0; s < 4; ++s) {
            float v = sacc[s];
            v += __shfl_xor_sync(0xffffffffu, v, 1);
            v += __shfl_xor_sync(0xffffffffu, v, 2);
            if (q == 0) {
                int mf = s >> 1, rp = s & 1;
                int r_ = m0 + warp_m * 32 + mf * 16 + g4 + rp * 8;
                atomicAdd(&g_scores[(r_ & 127) * TT + (r_ >> 7)], v);
            }
        }
    }
}

// ---------------------------------------------------------------
// Recurrence v7 (R14 structure — proven at 2930us): tensor-core matvec,
// fp16 hi/lo exchange, per-warp single-flag polling, monolithic rebuild
// after the poll. Single delta vs R14: no __threadfence before st.release
// (syncthreads + release/acquire already carry the happens-before).
//
// SMEM: Whh 65536 | Whl 65536 | Ahh 8192 | Ahl 8192 | Dsm [16][132]f 8448
//       | lensm 64  => 155968 B
// ---------------------------------------------------------------
#define R3_WHH 0
#define R3_WHL 65536
#define R3_AHH 131072
#define R3_AHL 139264
#define R3_DSM 147456
#define R3_LEN 155904
#define REC3_SMEM 155968

__global__ void __launch_bounds__(256, 1)
rec3(const int* __restrict__ lengths,
     const float* __restrict__ whh_f, const float* __restrict__ whh_r,
     int layer) {
    extern __shared__ char smraw[];
    const uint32_t smb = s2u(smraw);
    float* Dsm = (float*)(smraw + R3_DSM);
    int* lensm = (int*)(smraw + R3_LEN);

    const int slice = blockIdx.x, bg = blockIdx.y, dir = blockIdx.z;
    const int tid = threadIdx.x;
    const int wid = tid >> 5;
    const int lane = tid & 31;
    const int gid = dir * NBG + bg;

    const float* __restrict__ whh = dir ? whh_r : whh_f;
    const float* __restrict__ xg = dir ? g_xgR : g_xgF;

    // ---- one-time W slice load + fp16 split into SW128 chunks ----
    {
        int n = tid >> 1;                              // local n row 0..127
        int grow = (n >> 5) * 256 + slice * 32 + (n & 31);
        int kh = (tid & 1) * 128;
        const float* src = whh + (size_t)grow * HH + kh;
#pragma unroll 8
        for (int kk = 0; kk < 128; kk += 2) {
            int k = kh + kk;
            float2 v = *(const float2*)(src + kk);
            __half2 hi = __float22half2_rn(v);
            float2 hif = __half22float2(hi);
            __half2 lo = __float22half2_rn(make_float2(v.x - hif.x, v.y - hif.y));
            int kc = k >> 6;
            uint32_t off = SW128((uint32_t)(n * 128 + (k & 63) * 2));
            *(__half2*)(smraw + R3_WHH + kc * 16384 + off) = hi;
            *(__half2*)(smraw + R3_WHL + kc * 16384 + off) = lo;
        }
    }
    // zero A chunks (h(-1) = 0)
    for (int i = tid; i < 2048; i += 256) {
        ((__half2*)(smraw + R3_AHH))[i] = __halves2half2(__float2half(0.f), __float2half(0.f));
        ((__half2*)(smraw + R3_AHL))[i] = __halves2half2(__float2half(0.f), __float2half(0.f));
    }
    if (tid < 16) {
        int l = lengths[bg * BPC + tid];
        lensm[tid] = l < 1 ? 1 : l;
    }
    __syncthreads();

    // frag addressing (identical pattern to gemm_tc)
    const int g4 = lane >> 2, q = lane & 3;
    const int rowb = wid * 16 + (lane & 7) + ((lane >> 4) << 3);
    const int kbb = ((lane >> 3) & 1) * 16;
    const int rowa = lane & 15;
    const int kba = (lane >> 4) * 16;

    // this lane's two frag n-columns and their xg columns
    int ncol[2], xcol[2];
#pragma unroll
    for (int f = 0; f < 2; ++f) {
        ncol[f] = wid * 16 + f * 8 + 2 * q;
        xcol[f] = ((ncol[f] >> 5) << 8) + slice * 32 + (ncol[f] & 31);
    }
    const int mrow0 = g4, mrow1 = g4 + 8;   // batch rows of the frags

    // pointwise slot
    const int my_bs = tid & 15;
    const int my_u2 = tid >> 4;
    const int my_u = slice * 32 + 2 * my_u2;
    unsigned* my_flag = &g_flag[(gid * SLICES + slice) * 32];
    const unsigned* warp_flag = &g_flag[(gid * SLICES + wid) * 32];

    // rebuild region: batch b = tid&15, k-range [k0, k0+16)
    const int rb_b = tid & 15;
    const int rb_k0 = (tid >> 4) * 16;
    const int rb_kc = rb_k0 >> 6;
    const uint32_t rb_off0 = SW128((uint32_t)(rb_b * 128 + (rb_k0 & 63) * 2));
    const uint32_t rb_off1 = SW128((uint32_t)(rb_b * 128 + (rb_k0 & 63) * 2 + 16));

    float c0 = 0.f, c1 = 0.f;

    // xg frag preload for t = 0
    float xf[2][4];
    {
        int len0 = lensm[mrow0], len1 = lensm[mrow1];
        int t0 = dir ? (len0 - 1) : 0;
        int t1 = dir ? (len1 - 1) : 0;
#pragma unroll
        for (int f = 0; f < 2; ++f) {
            float2 a = *(const float2*)(xg + ((size_t)t0 * BB + bg * BPC + mrow0) * GG + xcol[f]);
            float2 b = *(const float2*)(xg + ((size_t)t1 * BB + bg * BPC + mrow1) * GG + xcol[f]);
            xf[f][0] = a.x; xf[f][1] = a.y; xf[f][2] = b.x; xf[f][3] = b.y;
        }
    }

    for (int t = 0; t < TT; ++t) {
        // ---- tensor-core matvec: acc = xg + h·W^T (3-term fp16 split) ----
        float acc[2][4];
#pragma unroll
        for (int f = 0; f < 2; ++f)
#pragma unroll
            for (int i = 0; i < 4; ++i) acc[f][i] = xf[f][i];

#pragma unroll
        for (int kc = 0; kc < 4; ++kc) {
#pragma unroll
            for (int ks = 0; ks < 4; ++ks) {
                uint32_t ah[4], al[4], wh[4], wl[4];
                uint32_t ao = SW128((uint32_t)(rowa * 128 + ks * 32 + kba));
                LDSM4(ah, smb + R3_AHH + kc * 2048 + ao);
                LDSM4(al, smb + R3_AHL + kc * 2048 + ao);
                uint32_t bo = SW128((uint32_t)(rowb * 128 + ks * 32 + kbb));
                LDSM4(wh, smb + R3_WHH + kc * 16384 + bo);
                LDSM4(wl, smb + R3_WHL + kc * 16384 + bo);
                MMA16816(acc[0], ah, wh[0], wh[1]);
                MMA16816(acc[1], ah, wh[2], wh[3]);
                MMA16816(acc[0], al, wh[0], wh[1]);
                MMA16816(acc[1], al, wh[2], wh[3]);
                MMA16816(acc[0], ah, wl[0], wl[1]);
                MMA16816(acc[1], ah, wl[2], wl[3]);
            }
        }

        // ---- stage gates to Dsm ----
#pragma unroll
        for (int f = 0; f < 2; ++f) {
            *(float2*)&Dsm[mrow0 * 132 + ncol[f]] = make_float2(acc[f][0], acc[f][1]);
            *(float2*)&Dsm[mrow1 * 132 + ncol[f]] = make_float2(acc[f][2], acc[f][3]);
        }
        __syncthreads();

        // ---- pointwise LSTM cell for slot (my_bs, my_u2) ----
        float h0, h1;
        {
            float2 vgi = *(const float2*)&Dsm[my_bs * 132 + 0 * 32 + 2 * my_u2];
            float2 vgf = *(const float2*)&Dsm[my_bs * 132 + 1 * 32 + 2 * my_u2];
            float2 vgc = *(const float2*)&Dsm[my_bs * 132 + 2 * 32 + 2 * my_u2];
            float2 vgo = *(const float2*)&Dsm[my_bs * 132 + 3 * 32 + 2 * my_u2];
            float i0 = sigfast(vgi.x), i1 = sigfast(vgi.y);
            float f0 = sigfast(vgf.x), f1 = sigfast(vgf.y);
            float z0 = tanhfast(vgc.x), z1 = tanhfast(vgc.y);
            float o0 = sigfast(vgo.x), o1 = sigfast(vgo.y);
            c0 = f0 * c0 + i0 * z0;
            c1 = f1 * c1 + i1 * z1;
            h0 = o0 * tanhfast(c0);
            h1 = o1 * tanhfast(c1);
        }

        // fp16 hi/lo split of h (used for exchange AND global outputs)
        __half2 hi2, lo2;
        {
            __half h0h = __float2half_rn(h0);
            __half h1h = __float2half_rn(h1);
            hi2 = __halves2half2(h0h, h1h);
            lo2 = __halves2half2(__float2half_rn(h0 - __half2float(h0h)),
                                 __float2half_rn(h1 - __half2float(h1h)));
        }

        if (t + 1 < TT) {
            // exchange store (fp16 hi/lo) + release-arrive (no extra fence:
            // syncthreads + st.release/ld.acquire carry the happens-before)
            __stcg((uint32_t*)&g_hxh[t & 1][gid][my_bs][my_u], *(uint32_t*)&hi2);
            __stcg((uint32_t*)&g_hxl[t & 1][gid][my_bs][my_u], *(uint32_t*)&lo2);
            __syncthreads();
            if (tid == 0) st_rel(my_flag, (unsigned)(t + 1));
        }

        // ---- global outputs + xg frag prefetch (hidden in peers' window) ----
        {
            int len = lensm[my_bs];
            int tin = dir ? ((t < len) ? (len - 1 - t) : t) : t;
            size_t aoff2 = ((size_t)tin * BB + bg * BPC + my_bs) * HH2 + dir * HH + my_u;
            *(__half2*)(g_ahh + aoff2) = hi2;
            *(__half2*)(g_ahl + aoff2) = lo2;
            if (layer)
                *(float2*)(g_h2 + aoff2) = make_float2(h0, h1);
        }

        if (t + 1 < TT) {
            {
                int tn = t + 1;
                int len0 = lensm[mrow0], len1 = lensm[mrow1];
                int t0 = dir ? ((tn < len0) ? (len0 - 1 - tn) : tn) : tn;
                int t1 = dir ? ((tn < len1) ? (len1 - 1 - tn) : tn) : tn;
#pragma unroll
                for (int f = 0; f < 2; ++f) {
                    float2 a = *(const float2*)(xg + ((size_t)t0 * BB + bg * BPC + mrow0) * GG + xcol[f]);
                    float2 b = *(const float2*)(xg + ((size_t)t1 * BB + bg * BPC + mrow1) * GG + xcol[f]);
                    xf[f][0] = a.x; xf[f][1] = a.y; xf[f][2] = b.x; xf[f][3] = b.y;
                }
            }

            // ---- per-warp poll: warp wid consumes slice wid's k-region ----
            {
                unsigned target = (unsigned)(t + 1);
                while (ld_acq(warp_flag) < target) {}
            }

            // ---- rebuild A chunks: direct fp16 copy from exchange ----
            {
                const uint4* srcH = (const uint4*)&g_hxh[t & 1][gid][rb_b][rb_k0];
                const uint4* srcL = (const uint4*)&g_hxl[t & 1][gid][rb_b][rb_k0];
                uint4 vh0 = __ldcg(srcH);
                uint4 vh1 = __ldcg(srcH + 1);
                uint4 vl0 = __ldcg(srcL);
                uint4 vl1 = __ldcg(srcL + 1);
                *(uint4*)(smraw + R3_AHH + rb_kc * 2048 + rb_off0) = vh0;
                *(uint4*)(smraw + R3_AHH + rb_kc * 2048 + rb_off1) = vh1;
                *(uint4*)(smraw + R3_AHL + rb_kc * 2048 + rb_off0) = vl0;
                *(uint4*)(smraw + R3_AHL + rb_kc * 2048 + rb_off1) = vl1;
            }
            __syncthreads();
        }
    }
}

// ---------------------------------------------------------------
__global__ void zero_scores() {
    int i = blockIdx.x * blockDim.x + threadIdx.x;
    if (i < BB * TT) g_scores[i] = 0.f;
}

// ---------------------------------------------------------------
// Masked softmax over time + weighted sum of h2 -> out [B, 2H].
// ---------------------------------------------------------------
__global__ void __launch_bounds__(256)
attn_out(const int* __restrict__ lengths, float* __restrict__ out) {
    int b = blockIdx.x;
    int tid = threadIdx.x;
    __shared__ float red[256];
    __shared__ float w[256];

    int len = lengths[b];
    if (len < 1) len = 1;

    float s = (tid < len) ? g_scores[b * TT + tid] : -3.0e38f;
    red[tid] = s;
    __syncthreads();
    for (int o = 128; o > 0; o >>= 1) {
        if (tid < o) red[tid] = fmaxf(red[tid], red[tid + o]);
        __syncthreads();
    }
    float mx = red[0];
    __syncthreads();
    float e = (tid < len) ? expf(s - mx) : 0.f;
    red[tid] = e;
    __syncthreads();
    for (int o = 128; o > 0; o >>= 1) {
        if (tid < o) red[tid] += red[tid + o];
        __syncthreads();
    }
    float inv = 1.f / red[0];
    w[tid] = e * inv;
    __syncthreads();

    for (int d = tid; d < HH2; d += 256) {
        float acc = 0.f;
        for (int t = 0; t < len; ++t)
            acc += w[t] * g_h2[((size_t)t * BB + b) * HH2 + d];
        out[b * HH2 + d] = acc;
    }
}

// ---------------------------------------------------------------
extern "C" void kernel_launch(void* const* d_in, const int* in_sizes, int n_in,
                              void* d_out, int out_size) {
    const float* x        = (const float*)d_in[0];
    const int*   lengths  = (const int*)d_in[1];
    const float* w_ih_l0  = (const float*)d_in[2];
    const float* w_hh_l0  = (const float*)d_in[3];
    const float* b_ih_l0  = (const float*)d_in[4];
    const float* b_hh_l0  = (const float*)d_in[5];
    const float* w_ih_l0r = (const float*)d_in[6];
    const float* w_hh_l0r = (const float*)d_in[7];
    const float* b_ih_l0r = (const float*)d_in[8];
    const float* b_hh_l0r = (const float*)d_in[9];
    const float* w_ih_l1  = (const float*)d_in[10];
    const float* w_hh_l1  = (const float*)d_in[11];
    const float* b_ih_l1  = (const float*)d_in[12];
    const float* b_hh_l1  = (const float*)d_in[13];
    const float* w_ih_l1r = (const float*)d_in[14];
    const float* w_hh_l1r = (const float*)d_in[15];
    const float* b_ih_l1r = (const float*)d_in[16];
    const float* b_hh_l1r = (const float*)d_in[17];
    const float* mlp_w    = (const float*)d_in[18];
    const float* mlp_b    = (const float*)d_in[19];
    const float* ctx      = (const float*)d_in[20];
    float* out = (float*)d_out;

    static int attr_set = 0;
    if (!attr_set) {
        cudaFuncSetAttribute(rec3, cudaFuncAttributeMaxDynamicSharedMemorySize, REC3_SMEM);
        cudaFuncSetAttribute(gemm_tc, cudaFuncAttributeMaxDynamicSharedMemorySize, GT_SMEM);
        attr_set = 1;
    }

    __half *wbh, *wbl, *axh, *axl;
    cudaGetSymbolAddress((void**)&wbh, g_wbh);
    cudaGetSymbolAddress((void**)&wbl, g_wbl);
    cudaGetSymbolAddress((void**)&axh, g_axh);
    cudaGetSymbolAddress((void**)&axl, g_axl);

    // converts needed for layer-0 GEMMs
    conv_split<<<(TBROWS * KPAD0 + 255) / 256, 256>>>(x, axh, axl, DD, KPAD0, TBROWS);
    conv_split<<<(1024 * KPAD0 + 255) / 256, 256>>>(w_ih_l0,  wbh + OFF_L0F, wbl + OFF_L0F, DD, KPAD0, 1024);
    conv_split<<<(1024 * KPAD0 + 255) / 256, 256>>>(w_ih_l0r, wbh + OFF_L0R, wbl + OFF_L0R, DD, KPAD0, 1024);

    // layer-0 projection GEMMs: fwd+rev fused in one launch (z selects)
    gemm_tc<<<dim3(256, 8, 2), 256, GT_SMEM>>>(0, OFF_L0F, KPAD0, 5, 0,
                                               b_ih_l0, b_hh_l0, nullptr,
                                               OFF_L0R, b_ih_l0r, b_hh_l0r);

    // remaining weight converts
    conv_split<<<(1024 * KPAD1 + 255) / 256, 256>>>(w_ih_l1,  wbh + OFF_L1F, wbl + OFF_L1F, HH2, KPAD1, 1024);
    conv_split<<<(1024 * KPAD1 + 255) / 256, 256>>>(w_ih_l1r, wbh + OFF_L1R, wbl + OFF_L1R, HH2, KPAD1, 1024);

    // layer-0 recurrence (tensor-core matvec)
    zero_flags<<<16, 256>>>();
    rec3<<<dim3(SLICES, NBG, 2), 256, REC3_SMEM>>>(lengths, w_hh_l0, w_hh_l0r, 0);

    // layer-1 projection GEMMs: fwd+rev fused in one launch
    gemm_tc<<<dim3(256, 8, 2), 256, GT_SMEM>>>(1, OFF_L1F, KPAD1, 8, 0,
                                               b_ih_l1, b_hh_l1, nullptr,
                                               OFF_L1R, b_ih_l1r, b_hh_l1r);

    // layer-1 recurrence
    zero_flags<<<16, 256>>>();
    rec3<<<dim3(SLICES, NBG, 2), 256, REC3_SMEM>>>(lengths, w_hh_l1, w_hh_l1r, 1);

    // attention
    conv_split<<<(512 * KPAD1 + 255) / 256, 256>>>(mlp_w, wbh + OFF_MLP, wbl + OFF_MLP, HH2, KPAD1, 512);
    zero_scores<<<32, 1024>>>();
    gemm_tc<<<dim3(256, 4, 1), 256, GT_SMEM>>>(1, OFF_MLP, KPAD1, 8, 2,
                                               mlp_b, nullptr, ctx,
                                               OFF_MLP, nullptr, nullptr);
    attn_out<<<128, 256>>>(lengths, out);
}

// round 17
// speedup vs baseline: 1.4858x; 1.0580x over previous
#include <cuda_runtime.h>
#include <cuda_fp16.h>
#include <stdint.h>
#include <math.h>

// Problem constants
#define TT 256
#define BB 128
#define DD 300
#define HH 256
#define GG 1024   // 4*H
#define HH2 512   // 2*H
#define TBROWS 32768  // T*B

#define SLICES 8   // rec: n-slices of hidden dim (32 units each)
#define NBG 8      // rec: batch groups
#define BPC 16     // rec: batches per CTA

#define KPAD0 320  // layer-0 K (300) padded to mult of 64
#define KPAD1 512

typedef unsigned long long ull;

// -------- static device scratch (no allocation allowed) --------
__device__ float g_xgF[TBROWS * (size_t)GG];
__device__ float g_xgR[TBROWS * (size_t)GG];
__device__ float g_h2[TBROWS * (size_t)HH2];
__device__ float g_scores[BB * TT];

// fp16 split operand buffers
__device__ __half g_axh[TBROWS * (size_t)KPAD0];   // x hi
__device__ __half g_axl[TBROWS * (size_t)KPAD0];   // x lo
__device__ __half g_ahh[TBROWS * (size_t)KPAD1];   // h1/h2 hi (written by rec3)
__device__ __half g_ahl[TBROWS * (size_t)KPAD1];   // h1/h2 lo (written by rec3)

// weight buffers (element offsets); only hi used by GEMMs
#define OFF_L0F 0
#define OFF_L0R 327680                    // 1024*320
#define OFF_L1F 655360
#define OFF_L1R 1179648                   // + 1024*512
#define OFF_MLP 1703936
#define WBUF_SZ 1966080
__device__ __half g_wbh[WBUF_SZ];
__device__ __half g_wbl[WBUF_SZ];

// rec h exchange: fp16 hi/lo [parity][group][b][u]
__device__ __half g_hxh[2][16][BPC][256];
__device__ __half g_hxl[2][16][BPC][256];
// per-CTA arrival flags: [group][slice][32-uint pad] (one 128B line each)
__device__ unsigned g_flag[16 * SLICES * 32];

// ---------------- misc helpers ----------------
__device__ __forceinline__ unsigned ld_acq(const unsigned* p) {
    unsigned v;
    asm volatile("ld.acquire.gpu.global.b32 %0, [%1];" : "=r"(v) : "l"(p) : "memory");
    return v;
}
__device__ __forceinline__ void st_rel(unsigned* p, unsigned v) {
    asm volatile("st.release.gpu.global.b32 [%0], %1;" :: "l"(p), "r"(v) : "memory");
}
__device__ __forceinline__ float sigfast(float x) {
    return __fdividef(1.f, 1.f + __expf(-x));
}
__device__ __forceinline__ float tanhfast(float x) {
    return __fmaf_rn(2.f, __fdividef(1.f, 1.f + __expf(-2.f * x)), -1.f);
}

// ---------------- mma.sync / ldmatrix / cp.async helpers ----------------
__device__ __forceinline__ uint32_t s2u(const void* p) {
    uint32_t a;
    asm("{ .reg .u64 t; cvta.to.shared.u64 t, %1; cvt.u32.u64 %0, t; }" : "=r"(a) : "l"(p));
    return a;
}
__device__ __forceinline__ void cp16(uint32_t s, const void* g) {
    asm volatile("cp.async.cg.shared.global [%0], [%1], 16;" :: "r"(s), "l"(g));
}
#define CP_COMMIT() asm volatile("cp.async.commit_group;" ::: "memory")
#define CP_WAIT1()  asm volatile("cp.async.wait_group 1;" ::: "memory")
#define CP_WAIT0()  asm volatile("cp.async.wait_group 0;" ::: "memory")

#define LDSM4(r, addr) \
    asm volatile("ldmatrix.sync.aligned.m8n8.x4.shared.b16 {%0,%1,%2,%3}, [%4];" \
        : "=r"((r)[0]), "=r"((r)[1]), "=r"((r)[2]), "=r"((r)[3]) : "r"(addr))

#define MMA16816(c, a, b0v, b1v) \
    asm volatile("mma.sync.aligned.m16n8k16.row.col.f32.f16.f16.f32 " \
        "{%0,%1,%2,%3}, {%4,%5,%6,%7}, {%8,%9}, {%0,%1,%2,%3};" \
        : "+f"((c)[0]), "+f"((c)[1]), "+f"((c)[2]), "+f"((c)[3]) \
        : "r"((a)[0]), "r"((a)[1]), "r"((a)[2]), "r"((a)[3]), "r"(b0v), "r"(b1v))

#define SW128(off) ((off) ^ (((off) >> 3) & 0x70))

// ---------------------------------------------------------------
__global__ void zero_flags() {
    int i = blockIdx.x * blockDim.x + threadIdx.x;
    if (i < 16 * SLICES * 32) g_flag[i] = 0u;
}

// ---------------------------------------------------------------
// fp32 -> fp16 hi/lo split with K zero-padding
// ---------------------------------------------------------------
__global__ void conv_split(const float* __restrict__ in,
                           __half* __restrict__ oh,
                           __half* __restrict__ ol,
                           int K, int Kpad, int rows) {
    size_t idx = (size_t)blockIdx.x * blockDim.x + threadIdx.x;
    size_t total = (size_t)rows * Kpad;
    if (idx >= total) return;
    int k = (int)(idx % Kpad);
    size_t row = idx / Kpad;
    float v = (k < K) ? in[row * K + k] : 0.f;
    __half h = __float2half_rn(v);
    oh[idx] = h;
    ol[idx] = __float2half_rn(v - __half2float(h));
}

// ---------------------------------------------------------------
// Tensor-core GEMM (mma.sync fp16, 2-term split AhWh + AlWh).
// gridDim.z selects fwd/rev weight set + destination (z=1 -> rev).
// dst_sel=2 = attention scores path (launch with gridDim.z=1).
// ---------------------------------------------------------------
#define GT_STAGE 49152
#define GT_SMEM (2 * GT_STAGE)   // 98304

__global__ void __launch_bounds__(256, 2)
gemm_tc(int a_sel, int woff, int Kpad, int nc, int dst_sel,
        const float* __restrict__ bias1, const float* __restrict__ bias2,
        const float* __restrict__ ctx,
        int woffR,
        const float* __restrict__ bias1R, const float* __restrict__ bias2R) {
    extern __shared__ char sm[];
    const uint32_t smb = s2u(sm);
    const int tid = threadIdx.x;
    const int lane = tid & 31;
    const int wid = tid >> 5;
    const int warp_m = wid & 3;
    const int warp_n = wid >> 2;

    if (blockIdx.z == 1) {
        woff = woffR;
        bias1 = bias1R;
        bias2 = bias2R;
        dst_sel = 1;
    }

    const __half* __restrict__ Ah = a_sel ? g_ahh : g_axh;
    const __half* __restrict__ Al = a_sel ? g_ahl : g_axl;
    const __half* __restrict__ Wh = g_wbh + woff;

    const int m0 = blockIdx.x * 128;
    const int n0 = blockIdx.y * 128;

    const int lrow = tid >> 1;
    const int lj0 = (tid & 1) * 4;
    const size_t aoff = (size_t)(m0 + lrow) * Kpad;
    const size_t woff2 = (size_t)(n0 + lrow) * Kpad;

    float acc[2][8][4];
#pragma unroll
    for (int i = 0; i < 2; ++i)
#pragma unroll
        for (int j = 0; j < 8; ++j)
#pragma unroll
            for (int k = 0; k < 4; ++k) acc[i][j][k] = 0.f;

    {
        const uint4* pAh = (const uint4*)(Ah + aoff);
        const uint4* pAl = (const uint4*)(Al + aoff);
        const uint4* pWh = (const uint4*)(Wh + woff2);
#pragma unroll
        for (int j = 0; j < 4; ++j) {
            uint32_t so = SW128((uint32_t)(lrow * 128 + (lj0 + j) * 16));
            cp16(smb + so,         pAh + lj0 + j);
            cp16(smb + 16384 + so, pAl + lj0 + j);
            cp16(smb + 32768 + so, pWh + lj0 + j);
        }
        CP_COMMIT();
    }

    for (int c = 0; c < nc; ++c) {
        if (c + 1 < nc) {
            uint32_t sb = smb + ((c + 1) & 1) * GT_STAGE;
            const uint4* pAh = (const uint4*)(Ah + aoff + (c + 1) * 64);
            const uint4* pAl = (const uint4*)(Al + aoff + (c + 1) * 64);
            const uint4* pWh = (const uint4*)(Wh + woff2 + (c + 1) * 64);
#pragma unroll
            for (int j = 0; j < 4; ++j) {
                uint32_t so = SW128((uint32_t)(lrow * 128 + (lj0 + j) * 16));
                cp16(sb + so,         pAh + lj0 + j);
                cp16(sb + 16384 + so, pAl + lj0 + j);
                cp16(sb + 32768 + so, pWh + lj0 + j);
            }
            CP_COMMIT();
            CP_WAIT1();
        } else {
            CP_WAIT0();
        }
        __syncthreads();

        const uint32_t bb = smb + (c & 1) * GT_STAGE;
        const int rowb_base = warp_n * 64 + (lane & 7) + ((lane >> 4) << 3);
        const int kbb_half = ((lane >> 3) & 1) * 16;
        const int rowa_base = warp_m * 32 + (lane & 15);
        const int kba_half = (lane >> 4) * 16;

#pragma unroll
        for (int ks = 0; ks < 4; ++ks) {
            uint32_t ah[2][4], al[2][4], wh[4][4];
            const int kba = ks * 32 + kba_half;
#pragma unroll
            for (int mf = 0; mf < 2; ++mf) {
                uint32_t off = SW128((uint32_t)((rowa_base + mf * 16) * 128 + kba));
                LDSM4(ah[mf], bb + off);
                LDSM4(al[mf], bb + 16384 + off);
            }
            const int kbbs = ks * 32 + kbb_half;
#pragma unroll
            for (int nf4 = 0; nf4 < 4; ++nf4) {
                uint32_t off = SW128((uint32_t)((rowb_base + nf4 * 16) * 128 + kbbs));
                LDSM4(wh[nf4], bb + 32768 + off);
            }
#pragma unroll
            for (int nf4 = 0; nf4 < 4; ++nf4)
#pragma unroll
                for (int mf = 0; mf < 2; ++mf) {
                    MMA16816(acc[mf][nf4 * 2],     ah[mf], wh[nf4][0], wh[nf4][1]);
                    MMA16816(acc[mf][nf4 * 2 + 1], ah[mf], wh[nf4][2], wh[nf4][3]);
                }
#pragma unroll
            for (int nf4 = 0; nf4 < 4; ++nf4)
#pragma unroll
                for (int mf = 0; mf < 2; ++mf) {
                    MMA16816(acc[mf][nf4 * 2],     al[mf], wh[nf4][0], wh[nf4][1]);
                    MMA16816(acc[mf][nf4 * 2 + 1], al[mf], wh[nf4][2], wh[nf4][3]);
                }
        }
        __syncthreads();
    }

    const int g4 = lane >> 2, q = lane & 3;
    if (dst_sel < 2) {
        float* __restrict__ dst = dst_sel ? g_xgR : g_xgF;
#pragma unroll
        for (int nf = 0; nf < 8; ++nf) {
            int n = n0 + warp_n * 64 + nf * 8 + q * 2;
            float bv0 = bias1[n] + bias2[n];
            float bv1 = bias1[n + 1] + bias2[n + 1];
#pragma unroll
            for (int mf = 0; mf < 2; ++mf) {
                int r_ = m0 + warp_m * 32 + mf * 16 + g4;
                *(float2*)&dst[(size_t)r_ * GG + n] =
                    make_float2(acc[mf][nf][0] + bv0, acc[mf][nf][1] + bv1);
                *(float2*)&dst[(size_t)(r_ + 8) * GG + n] =
                    make_float2(acc[mf][nf][2] + bv0, acc[mf][nf][3] + bv1);
            }
        }
    } else {
        float sacc[4] = {0.f, 0.f, 0.f, 0.f};
#pragma unroll
        for (int nf = 0; nf < 8; ++nf) {
            int n = n0 + warp_n * 64 + nf * 8 + q * 2;
            float bv0 = bias1[n], bv1 = bias1[n + 1];
            float c0 = ctx[n], c1 = ctx[n + 1];
#pragma unroll
            for (int mf = 0; mf < 2; ++mf) {
                sacc[mf * 2 + 0] += tanhf(acc[mf][nf][0] + bv0) * c0
                                  + tanhf(acc[mf][nf][1] + bv1) * c1;
                sacc[mf * 2 + 1] += tanhf(acc[mf][nf][2] + bv0) * c0
                                  + tanhf(acc[mf][nf][3] + bv1) * c1;
            }
        }
#pragma unroll
        for (int s = 0; s < 4; ++s) {
            float v = sacc[s];
            v += __shfl_xor_sync(0xffffffffu, v, 1);
            v += __shfl_xor_sync(0xffffffffu, v, 2);
            if (q == 0) {
                int mf = s >> 1, rp = s & 1;
                int r_ = m0 + warp_m * 32 + mf * 16 + g4 + rp * 8;
                atomicAdd(&g_scores[(r_ & 127) * TT + (r_ >> 7)], v);
            }
        }
    }
}

// ---------------------------------------------------------------
// Recurrence v9 (R16 structure, 2-term split: AhWh + AlWh — W-lo dropped,
// matching the projection GEMMs' precision scheme).
//
// SMEM: Whh 65536 | Ahh 8192 | Ahl 8192 | Dsm [16][132]f 8448 | lensm 64
//       => 90432 B
// ---------------------------------------------------------------
#define R3_WHH 0
#define R3_AHH 65536
#define R3_AHL 73728
#define R3_DSM 81920
#define R3_LEN 90368
#define REC3_SMEM 90432

__global__ void __launch_bounds__(256, 1)
rec3(const int* __restrict__ lengths,
     const float* __restrict__ whh_f, const float* __restrict__ whh_r,
     int layer) {
    extern __shared__ char smraw[];
    const uint32_t smb = s2u(smraw);
    float* Dsm = (float*)(smraw + R3_DSM);
    int* lensm = (int*)(smraw + R3_LEN);

    const int slice = blockIdx.x, bg = blockIdx.y, dir = blockIdx.z;
    const int tid = threadIdx.x;
    const int wid = tid >> 5;
    const int lane = tid & 31;
    const int gid = dir * NBG + bg;

    const float* __restrict__ whh = dir ? whh_r : whh_f;
    const float* __restrict__ xg = dir ? g_xgR : g_xgF;

    // ---- one-time W slice load + fp16 (hi only) into SW128 chunks ----
    {
        int n = tid >> 1;                              // local n row 0..127
        int grow = (n >> 5) * 256 + slice * 32 + (n & 31);
        int kh = (tid & 1) * 128;
        const float* src = whh + (size_t)grow * HH + kh;
#pragma unroll 8
        for (int kk = 0; kk < 128; kk += 2) {
            int k = kh + kk;
            float2 v = *(const float2*)(src + kk);
            __half2 hi = __float22half2_rn(v);
            int kc = k >> 6;
            uint32_t off = SW128((uint32_t)(n * 128 + (k & 63) * 2));
            *(__half2*)(smraw + R3_WHH + kc * 16384 + off) = hi;
        }
    }
    // zero A chunks (h(-1) = 0)
    for (int i = tid; i < 2048; i += 256) {
        ((__half2*)(smraw + R3_AHH))[i] = __halves2half2(__float2half(0.f), __float2half(0.f));
        ((__half2*)(smraw + R3_AHL))[i] = __halves2half2(__float2half(0.f), __float2half(0.f));
    }
    if (tid < 16) {
        int l = lengths[bg * BPC + tid];
        lensm[tid] = l < 1 ? 1 : l;
    }
    __syncthreads();

    // frag addressing (identical pattern to gemm_tc)
    const int g4 = lane >> 2, q = lane & 3;
    const int rowb = wid * 16 + (lane & 7) + ((lane >> 4) << 3);
    const int kbb = ((lane >> 3) & 1) * 16;
    const int rowa = lane & 15;
    const int kba = (lane >> 4) * 16;

    // this lane's two frag n-columns and their xg columns
    int ncol[2], xcol[2];
#pragma unroll
    for (int f = 0; f < 2; ++f) {
        ncol[f] = wid * 16 + f * 8 + 2 * q;
        xcol[f] = ((ncol[f] >> 5) << 8) + slice * 32 + (ncol[f] & 31);
    }
    const int mrow0 = g4, mrow1 = g4 + 8;   // batch rows of the frags

    // pointwise slot
    const int my_bs = tid & 15;
    const int my_u2 = tid >> 4;
    const int my_u = slice * 32 + 2 * my_u2;
    unsigned* my_flag = &g_flag[(gid * SLICES + slice) * 32];
    const unsigned* warp_flag = &g_flag[(gid * SLICES + wid) * 32];

    // rebuild region: batch b = tid&15, k-range [k0, k0+16)
    const int rb_b = tid & 15;
    const int rb_k0 = (tid >> 4) * 16;
    const int rb_kc = rb_k0 >> 6;
    const uint32_t rb_off0 = SW128((uint32_t)(rb_b * 128 + (rb_k0 & 63) * 2));
    const uint32_t rb_off1 = SW128((uint32_t)(rb_b * 128 + (rb_k0 & 63) * 2 + 16));

    float c0 = 0.f, c1 = 0.f;

    // xg frag preload for t = 0
    float xf[2][4];
    {
        int len0 = lensm[mrow0], len1 = lensm[mrow1];
        int t0 = dir ? (len0 - 1) : 0;
        int t1 = dir ? (len1 - 1) : 0;
#pragma unroll
        for (int f = 0; f < 2; ++f) {
            float2 a = *(const float2*)(xg + ((size_t)t0 * BB + bg * BPC + mrow0) * GG + xcol[f]);
            float2 b = *(const float2*)(xg + ((size_t)t1 * BB + bg * BPC + mrow1) * GG + xcol[f]);
            xf[f][0] = a.x; xf[f][1] = a.y; xf[f][2] = b.x; xf[f][3] = b.y;
        }
    }

    for (int t = 0; t < TT; ++t) {
        // ---- tensor-core matvec: acc = xg + h·W^T (2-term fp16 split) ----
        float acc[2][4];
#pragma unroll
        for (int f = 0; f < 2; ++f)
#pragma unroll
            for (int i = 0; i < 4; ++i) acc[f][i] = xf[f][i];

#pragma unroll
        for (int kc = 0; kc < 4; ++kc) {
#pragma unroll
            for (int ks = 0; ks < 4; ++ks) {
                uint32_t ah[4], al[4], wh[4];
                uint32_t ao = SW128((uint32_t)(rowa * 128 + ks * 32 + kba));
                LDSM4(ah, smb + R3_AHH + kc * 2048 + ao);
                LDSM4(al, smb + R3_AHL + kc * 2048 + ao);
                uint32_t bo = SW128((uint32_t)(rowb * 128 + ks * 32 + kbb));
                LDSM4(wh, smb + R3_WHH + kc * 16384 + bo);
                MMA16816(acc[0], ah, wh[0], wh[1]);
                MMA16816(acc[1], ah, wh[2], wh[3]);
                MMA16816(acc[0], al, wh[0], wh[1]);
                MMA16816(acc[1], al, wh[2], wh[3]);
            }
        }

        // ---- stage gates to Dsm ----
#pragma unroll
        for (int f = 0; f < 2; ++f) {
            *(float2*)&Dsm[mrow0 * 132 + ncol[f]] = make_float2(acc[f][0], acc[f][1]);
            *(float2*)&Dsm[mrow1 * 132 + ncol[f]] = make_float2(acc[f][2], acc[f][3]);
        }
        __syncthreads();

        // ---- pointwise LSTM cell for slot (my_bs, my_u2) ----
        float h0, h1;
        {
            float2 vgi = *(const float2*)&Dsm[my_bs * 132 + 0 * 32 + 2 * my_u2];
            float2 vgf = *(const float2*)&Dsm[my_bs * 132 + 1 * 32 + 2 * my_u2];
            float2 vgc = *(const float2*)&Dsm[my_bs * 132 + 2 * 32 + 2 * my_u2];
            float2 vgo = *(const float2*)&Dsm[my_bs * 132 + 3 * 32 + 2 * my_u2];
            float i0 = sigfast(vgi.x), i1 = sigfast(vgi.y);
            float f0 = sigfast(vgf.x), f1 = sigfast(vgf.y);
            float z0 = tanhfast(vgc.x), z1 = tanhfast(vgc.y);
            float o0 = sigfast(vgo.x), o1 = sigfast(vgo.y);
            c0 = f0 * c0 + i0 * z0;
            c1 = f1 * c1 + i1 * z1;
            h0 = o0 * tanhfast(c0);
            h1 = o1 * tanhfast(c1);
        }

        // fp16 hi/lo split of h (used for exchange AND global outputs)
        __half2 hi2, lo2;
        {
            __half h0h = __float2half_rn(h0);
            __half h1h = __float2half_rn(h1);
            hi2 = __halves2half2(h0h, h1h);
            lo2 = __halves2half2(__float2half_rn(h0 - __half2float(h0h)),
                                 __float2half_rn(h1 - __half2float(h1h)));
        }

        if (t + 1 < TT) {
            // exchange store (fp16 hi/lo) + release-arrive
            __stcg((uint32_t*)&g_hxh[t & 1][gid][my_bs][my_u], *(uint32_t*)&hi2);
            __stcg((uint32_t*)&g_hxl[t & 1][gid][my_bs][my_u], *(uint32_t*)&lo2);
            __syncthreads();
            if (tid == 0) st_rel(my_flag, (unsigned)(t + 1));
        }

        // ---- global outputs + xg frag prefetch (hidden in peers' window) ----
        {
            int len = lensm[my_bs];
            int tin = dir ? ((t < len) ? (len - 1 - t) : t) : t;
            size_t aoff2 = ((size_t)tin * BB + bg * BPC + my_bs) * HH2 + dir * HH + my_u;
            *(__half2*)(g_ahh + aoff2) = hi2;
            *(__half2*)(g_ahl + aoff2) = lo2;
            if (layer)
                *(float2*)(g_h2 + aoff2) = make_float2(h0, h1);
        }

        if (t + 1 < TT) {
            {
                int tn = t + 1;
                int len0 = lensm[mrow0], len1 = lensm[mrow1];
                int t0 = dir ? ((tn < len0) ? (len0 - 1 - tn) : tn) : tn;
                int t1 = dir ? ((tn < len1) ? (len1 - 1 - tn) : tn) : tn;
#pragma unroll
                for (int f = 0; f < 2; ++f) {
                    float2 a = *(const float2*)(xg + ((size_t)t0 * BB + bg * BPC + mrow0) * GG + xcol[f]);
                    float2 b = *(const float2*)(xg + ((size_t)t1 * BB + bg * BPC + mrow1) * GG + xcol[f]);
                    xf[f][0] = a.x; xf[f][1] = a.y; xf[f][2] = b.x; xf[f][3] = b.y;
                }
            }

            // ---- per-warp poll: warp wid consumes slice wid's k-region ----
            {
                unsigned target = (unsigned)(t + 1);
                while (ld_acq(warp_flag) < target) {}
            }

            // ---- rebuild A chunks: direct fp16 copy from exchange ----
            {
                const uint4* srcH = (const uint4*)&g_hxh[t & 1][gid][rb_b][rb_k0];
                const uint4* srcL = (const uint4*)&g_hxl[t & 1][gid][rb_b][rb_k0];
                uint4 vh0 = __ldcg(srcH);
                uint4 vh1 = __ldcg(srcH + 1);
                uint4 vl0 = __ldcg(srcL);
                uint4 vl1 = __ldcg(srcL + 1);
                *(uint4*)(smraw + R3_AHH + rb_kc * 2048 + rb_off0) = vh0;
                *(uint4*)(smraw + R3_AHH + rb_kc * 2048 + rb_off1) = vh1;
                *(uint4*)(smraw + R3_AHL + rb_kc * 2048 + rb_off0) = vl0;
                *(uint4*)(smraw + R3_AHL + rb_kc * 2048 + rb_off1) = vl1;
            }
            __syncthreads();
        }
    }
}

// ---------------------------------------------------------------
__global__ void zero_scores() {
    int i = blockIdx.x * blockDim.x + threadIdx.x;
    if (i < BB * TT) g_scores[i] = 0.f;
}

// ---------------------------------------------------------------
// Masked softmax over time + weighted sum of h2 -> out [B, 2H].
// ---------------------------------------------------------------
__global__ void __launch_bounds__(256)
attn_out(const int* __restrict__ lengths, float* __restrict__ out) {
    int b = blockIdx.x;
    int tid = threadIdx.x;
    __shared__ float red[256];
    __shared__ float w[256];

    int len = lengths[b];
    if (len < 1) len = 1;

    float s = (tid < len) ? g_scores[b * TT + tid] : -3.0e38f;
    red[tid] = s;
    __syncthreads();
    for (int o = 128; o > 0; o >>= 1) {
        if (tid < o) red[tid] = fmaxf(red[tid], red[tid + o]);
        __syncthreads();
    }
    float mx = red[0];
    __syncthreads();
    float e = (tid < len) ? expf(s - mx) : 0.f;
    red[tid] = e;
    __syncthreads();
    for (int o = 128; o > 0; o >>= 1) {
        if (tid < o) red[tid] += red[tid + o];
        __syncthreads();
    }
    float inv = 1.f / red[0];
    w[tid] = e * inv;
    __syncthreads();

    for (int d = tid; d < HH2; d += 256) {
        float acc = 0.f;
        for (int t = 0; t < len; ++t)
            acc += w[t] * g_h2[((size_t)t * BB + b) * HH2 + d];
        out[b * HH2 + d] = acc;
    }
}

// ---------------------------------------------------------------
extern "C" void kernel_launch(void* const* d_in, const int* in_sizes, int n_in,
                              void* d_out, int out_size) {
    const float* x        = (const float*)d_in[0];
    const int*   lengths  = (const int*)d_in[1];
    const float* w_ih_l0  = (const float*)d_in[2];
    const float* w_hh_l0  = (const float*)d_in[3];
    const float* b_ih_l0  = (const float*)d_in[4];
    const float* b_hh_l0  = (const float*)d_in[5];
    const float* w_ih_l0r = (const float*)d_in[6];
    const float* w_hh_l0r = (const float*)d_in[7];
    const float* b_ih_l0r = (const float*)d_in[8];
    const float* b_hh_l0r = (const float*)d_in[9];
    const float* w_ih_l1  = (const float*)d_in[10];
    const float* w_hh_l1  = (const float*)d_in[11];
    const float* b_ih_l1  = (const float*)d_in[12];
    const float* b_hh_l1  = (const float*)d_in[13];
    const float* w_ih_l1r = (const float*)d_in[14];
    const float* w_hh_l1r = (const float*)d_in[15];
    const float* b_ih_l1r = (const float*)d_in[16];
    const float* b_hh_l1r = (const float*)d_in[17];
    const float* mlp_w    = (const float*)d_in[18];
    const float* mlp_b    = (const float*)d_in[19];
    const float* ctx      = (const float*)d_in[20];
    float* out = (float*)d_out;

    static int attr_set = 0;
    if (!attr_set) {
        cudaFuncSetAttribute(rec3, cudaFuncAttributeMaxDynamicSharedMemorySize, REC3_SMEM);
        cudaFuncSetAttribute(gemm_tc, cudaFuncAttributeMaxDynamicSharedMemorySize, GT_SMEM);
        attr_set = 1;
    }

    __half *wbh, *wbl, *axh, *axl;
    cudaGetSymbolAddress((void**)&wbh, g_wbh);
    cudaGetSymbolAddress((void**)&wbl, g_wbl);
    cudaGetSymbolAddress((void**)&axh, g_axh);
    cudaGetSymbolAddress((void**)&axl, g_axl);

    // converts needed for layer-0 GEMMs
    conv_split<<<(TBROWS * KPAD0 + 255) / 256, 256>>>(x, axh, axl, DD, KPAD0, TBROWS);
    conv_split<<<(1024 * KPAD0 + 255) / 256, 256>>>(w_ih_l0,  wbh + OFF_L0F, wbl + OFF_L0F, DD, KPAD0, 1024);
    conv_split<<<(1024 * KPAD0 + 255) / 256, 256>>>(w_ih_l0r, wbh + OFF_L0R, wbl + OFF_L0R, DD, KPAD0, 1024);

    // layer-0 projection GEMMs: fwd+rev fused in one launch (z selects)
    gemm_tc<<<dim3(256, 8, 2), 256, GT_SMEM>>>(0, OFF_L0F, KPAD0, 5, 0,
                                               b_ih_l0, b_hh_l0, nullptr,
                                               OFF_L0R, b_ih_l0r, b_hh_l0r);

    // remaining weight converts
    conv_split<<<(1024 * KPAD1 + 255) / 256, 256>>>(w_ih_l1,  wbh + OFF_L1F, wbl + OFF_L1F, HH2, KPAD1, 1024);
    conv_split<<<(1024 * KPAD1 + 255) / 256, 256>>>(w_ih_l1r, wbh + OFF_L1R, wbl + OFF_L1R, HH2, KPAD1, 1024);

    // layer-0 recurrence (tensor-core matvec, 2-term)
    zero_flags<<<16, 256>>>();
    rec3<<<dim3(SLICES, NBG, 2), 256, REC3_SMEM>>>(lengths, w_hh_l0, w_hh_l0r, 0);

    // layer-1 projection GEMMs: fwd+rev fused in one launch
    gemm_tc<<<dim3(256, 8, 2), 256, GT_SMEM>>>(1, OFF_L1F, KPAD1, 8, 0,
                                               b_ih_l1, b_hh_l1, nullptr,
                                               OFF_L1R, b_ih_l1r, b_hh_l1r);

    // layer-1 recurrence
    zero_flags<<<16, 256>>>();
    rec3<<<dim3(SLICES, NBG, 2), 256, REC3_SMEM>>>(lengths, w_hh_l1, w_hh_l1r, 1);

    // attention
    conv_split<<<(512 * KPAD1 + 255) / 256, 256>>>(mlp_w, wbh + OFF_MLP, wbl + OFF_MLP, HH2, KPAD1, 512);
    zero_scores<<<32, 1024>>>();
    gemm_tc<<<dim3(256, 4, 1), 256, GT_SMEM>>>(1, OFF_MLP, KPAD1, 8, 2,
                                               mlp_b, nullptr, ctx,
                                               OFF_MLP, nullptr, nullptr);
    attn_out<<<128, 256>>>(lengths, out);
}